// round 4
// baseline (speedup 1.0000x reference)
#include <cuda_runtime.h>

// GCN_42417097015629: 3-layer GCN + classifier on GB300 (sm_103a)
// N=200000 nodes, E=6400000 edges, dims 3 -> 6 -> 12 -> 24 -> 13.
//
// edge_index is INT32 (JAX default x64-disabled downcasts int64 -> int32).
// Reading it as int64 in rounds 1-3 produced garbage indices -> 717 traps.
//
// Atomic-free aggregation via per-call CSR build:
//   count in-deg -> dinv -> 3-kernel scan -> scatter (src,norm) CSR
//   per layer: node kernel (activation + @W), warp-per-node CSR gather (+self-loop,+bias)
//   final: l2norm -> @Wc+bc -> l2norm -> d_out

constexpr int N_ = 200000;
constexpr int E_ = 6400000;
constexpr int NB_ = (N_ + 255) / 256;   // 782 scan blocks
constexpr float EPS_ = 1e-12f;

__device__ int   g_cnt[N_];        // real in-degree
__device__ int   g_cur[N_];        // scatter cursors
__device__ int   g_row[N_ + 1];    // CSR row starts
__device__ int   g_bsum[1024];     // scan block sums
__device__ float g_dinv[N_];
__device__ int2  g_csr[E_];        // (src, norm as float bits), bucketed by dst
__device__ float g_bufA[(size_t)N_ * 24];
__device__ float g_bufB[(size_t)N_ * 24];

// ---------------------------------------------------------------------------
// CSR build
// ---------------------------------------------------------------------------

__global__ void k_init() {
    int i = blockIdx.x * blockDim.x + threadIdx.x;
    if (i < N_) { g_cnt[i] = 0; g_cur[i] = 0; }
}

__global__ void k_count(const int* __restrict__ ei) {
    int e = blockIdx.x * blockDim.x + threadIdx.x;
    if (e >= E_) return;
    int d = ei[E_ + e];
    atomicAdd(&g_cnt[d], 1);
}

__global__ void k_dinv() {
    int i = blockIdx.x * blockDim.x + threadIdx.x;
    if (i < N_) g_dinv[i] = rsqrtf((float)(g_cnt[i] + 1));  // +1 self-loop
}

__global__ void k_scan1() {
    __shared__ int sm[256];
    int tid = threadIdx.x;
    int i = blockIdx.x * 256 + tid;
    int v = (i < N_) ? g_cnt[i] : 0;
    sm[tid] = v;
    __syncthreads();
    #pragma unroll
    for (int off = 1; off < 256; off <<= 1) {
        int t = (tid >= off) ? sm[tid - off] : 0;
        __syncthreads();
        sm[tid] += t;
        __syncthreads();
    }
    if (i < N_) g_row[i] = sm[tid] - v;           // exclusive within block
    if (tid == 255) g_bsum[blockIdx.x] = sm[255]; // block total
}

__global__ void k_scan2() {  // 1 block, 1024 threads
    __shared__ int sm[1024];
    int tid = threadIdx.x;
    int v = (tid < NB_) ? g_bsum[tid] : 0;
    sm[tid] = v;
    __syncthreads();
    #pragma unroll
    for (int off = 1; off < 1024; off <<= 1) {
        int t = (tid >= off) ? sm[tid - off] : 0;
        __syncthreads();
        sm[tid] += t;
        __syncthreads();
    }
    if (tid < NB_) g_bsum[tid] = sm[tid] - v;     // exclusive block offsets
}

__global__ void k_scan3() {
    int i = blockIdx.x * blockDim.x + threadIdx.x;
    if (i < N_) g_row[i] += g_bsum[i >> 8];
    if (i == 0) g_row[N_] = E_;
}

__global__ void k_scatter(const int* __restrict__ ei) {
    int e = blockIdx.x * blockDim.x + threadIdx.x;
    if (e >= E_) return;
    int s = ei[e];
    int d = ei[E_ + e];
    int slot = g_row[d] + atomicAdd(&g_cur[d], 1);
    float norm = g_dinv[s] * g_dinv[d];
    g_csr[slot] = make_int2(s, __float_as_int(norm));
}

// ---------------------------------------------------------------------------
// Warp-per-node CSR aggregation: out[i] = sum_e norm_e*h[src_e] + dinv_i^2*h[i] + b
// ---------------------------------------------------------------------------

template <int F>
__device__ __forceinline__ void agg_body(const float* __restrict__ hin,
                                         const float* __restrict__ b,
                                         float* __restrict__ out) {
    int gwarp = (blockIdx.x * blockDim.x + threadIdx.x) >> 5;
    int lane = threadIdx.x & 31;
    if (gwarp >= N_) return;
    int start = g_row[gwarp];
    int end   = g_row[gwarp + 1];
    float acc = 0.f;
    for (int j = start; j < end; j++) {
        int2 e = g_csr[j];                       // uniform (broadcast) load
        if (lane < F) {
            float v = hin[(size_t)e.x * F + lane];
            acc = fmaf(__int_as_float(e.y), v, acc);
        }
    }
    if (lane < F) {
        float di = g_dinv[gwarp];
        float h = hin[(size_t)gwarp * F + lane];
        out[(size_t)gwarp * F + lane] = acc + di * di * h + b[lane];
    }
}

__global__ void k_agg6(const float* b)  { agg_body<6>(g_bufA, b, g_bufB); }
__global__ void k_agg12(const float* b) { agg_body<12>(g_bufA, b, g_bufB); }
__global__ void k_agg24(const float* b) { agg_body<24>(g_bufA, b, g_bufB); }

// ---------------------------------------------------------------------------
// Node kernels (activations + dense transforms; tiny relative to edge work)
// ---------------------------------------------------------------------------

// Layer 1: bufA = x @ W1 (3->6)
__global__ void k_node1(const float* __restrict__ x,
                        const float* __restrict__ W) {
    int i = blockIdx.x * blockDim.x + threadIdx.x;
    if (i >= N_) return;
    float in0 = x[3 * i], in1 = x[3 * i + 1], in2 = x[3 * i + 2];
    #pragma unroll
    for (int o = 0; o < 6; o++)
        g_bufA[(size_t)i * 6 + o] = fmaf(in0, W[o], fmaf(in1, W[6 + o], in2 * W[12 + o]));
}

// Layer 2 prep: bufA = tanh(bufB) @ W2 (6->12)
__global__ void k_node2(const float* __restrict__ W) {
    int i = blockIdx.x * blockDim.x + threadIdx.x;
    if (i >= N_) return;
    float hin[6];
    #pragma unroll
    for (int k = 0; k < 6; k++) hin[k] = tanhf(g_bufB[(size_t)i * 6 + k]);
    #pragma unroll
    for (int o = 0; o < 12; o++) {
        float acc = 0.f;
        #pragma unroll
        for (int k = 0; k < 6; k++) acc = fmaf(hin[k], W[k * 12 + o], acc);
        g_bufA[(size_t)i * 12 + o] = acc;
    }
}

// Layer 3 prep: bufA = tanh(l2norm(bufB)) @ W3 (12->24)
__global__ void k_node3(const float* __restrict__ W) {
    int i = blockIdx.x * blockDim.x + threadIdx.x;
    if (i >= N_) return;
    float hin[12];
    float ss = 0.f;
    #pragma unroll
    for (int k = 0; k < 12; k++) {
        float v = g_bufB[(size_t)i * 12 + k];
        hin[k] = v;
        ss = fmaf(v, v, ss);
    }
    float sc = 1.f / fmaxf(sqrtf(ss), EPS_);
    #pragma unroll
    for (int k = 0; k < 12; k++) hin[k] = tanhf(hin[k] * sc);
    #pragma unroll
    for (int o = 0; o < 24; o++) {
        float acc = 0.f;
        #pragma unroll
        for (int k = 0; k < 12; k++) acc = fmaf(hin[k], W[k * 24 + o], acc);
        g_bufA[(size_t)i * 24 + o] = acc;
    }
}

// Final: out = l2norm( l2norm(bufB) @ Wc + bc )
__global__ void k_final(const float* __restrict__ W,
                        const float* __restrict__ b,
                        float* __restrict__ out) {
    int i = blockIdx.x * blockDim.x + threadIdx.x;
    if (i >= N_) return;
    float v[24];
    float ss = 0.f;
    #pragma unroll
    for (int k = 0; k < 24; k++) {
        float t = g_bufB[(size_t)i * 24 + k];
        v[k] = t;
        ss = fmaf(t, t, ss);
    }
    float sc = 1.f / fmaxf(sqrtf(ss), EPS_);
    #pragma unroll
    for (int k = 0; k < 24; k++) v[k] *= sc;

    float y[13];
    float ss2 = 0.f;
    #pragma unroll
    for (int o = 0; o < 13; o++) {
        float acc = b[o];
        #pragma unroll
        for (int k = 0; k < 24; k++) acc = fmaf(v[k], W[k * 13 + o], acc);
        y[o] = acc;
        ss2 = fmaf(acc, acc, ss2);
    }
    float sc2 = 1.f / fmaxf(sqrtf(ss2), EPS_);
    #pragma unroll
    for (int o = 0; o < 13; o++) out[(size_t)i * 13 + o] = y[o] * sc2;
}

// ---------------------------------------------------------------------------
// Launch
// ---------------------------------------------------------------------------

extern "C" void kernel_launch(void* const* d_in, const int* in_sizes, int n_in,
                              void* d_out, int out_size) {
    const float* x  = (const float*)d_in[0];
    const int*   ei = (const int*)d_in[1];     // int32 [2, E]
    const float* W1 = (const float*)d_in[2];
    const float* b1 = (const float*)d_in[3];
    const float* W2 = (const float*)d_in[4];
    const float* b2 = (const float*)d_in[5];
    const float* W3 = (const float*)d_in[6];
    const float* b3 = (const float*)d_in[7];
    const float* Wc = (const float*)d_in[8];
    const float* bc = (const float*)d_in[9];
    float* out = (float*)d_out;

    const int TB = 256;
    const int GN = (N_ + TB - 1) / TB;       // 782
    const int GE = (E_ + TB - 1) / TB;       // 25000
    const int GW = (N_ * 32 + TB - 1) / TB;  // warp-per-node grids: 25000

    // CSR build
    k_init<<<GN, TB>>>();
    k_count<<<GE, TB>>>(ei);
    k_dinv<<<GN, TB>>>();
    k_scan1<<<NB_, 256>>>();
    k_scan2<<<1, 1024>>>();
    k_scan3<<<GN, TB>>>();
    k_scatter<<<GE, TB>>>(ei);

    // Layer 1 (3->6)
    k_node1<<<GN, TB>>>(x, W1);
    k_agg6<<<GW, TB>>>(b1);
    // Layer 2 (6->12)
    k_node2<<<GN, TB>>>(W2);
    k_agg12<<<GW, TB>>>(b2);
    // Layer 3 (12->24)
    k_node3<<<GN, TB>>>(W3);
    k_agg24<<<GW, TB>>>(b3);
    // Classifier (24->13)
    k_final<<<GN, TB>>>(Wc, bc, out);
}